// round 5
// baseline (speedup 1.0000x reference)
#include <cuda_runtime.h>

#define MEM_M 131072
#define E 512

typedef unsigned long long u64;

// ---- device scratch (no allocation allowed) ----
__device__ __align__(16) float g_kpart[3 * 32 * E];   // key GEMV partials
__device__ __align__(16) float g_rkeyn[E];            // r_key / ||r_key||
__device__ __align__(16) float g_wkeyn[E];            // w_key / ||w_key||
__device__ __align__(16) float g_erase[E];
__device__ __align__(16) float g_accA[E];             // sum sims_r * mem
__device__ __align__(16) float g_accB[E];             // sum sims_r * sims_w * mem
__device__ float g_S[2];                              // S_r, S_w

__device__ __forceinline__ float warp_sum(float v) {
#pragma unroll
    for (int o = 16; o; o >>= 1) v += __shfl_xor_sync(0xffffffffu, v, o);
    return v;
}

// ---- packed f32x2 helpers (sm_103a native FFMA2) ----
__device__ __forceinline__ u64 pk2(float lo, float hi) {
    u64 r; asm("mov.b64 %0, {%1, %2};" : "=l"(r) : "f"(lo), "f"(hi)); return r;
}
__device__ __forceinline__ float hadd2(u64 v) {
    float lo, hi; asm("mov.b64 {%0, %1}, %2;" : "=f"(lo), "=f"(hi) : "l"(v));
    return lo + hi;
}
__device__ __forceinline__ u64 fma2(u64 a, u64 b, u64 c) {
    u64 r; asm("fma.rn.f32x2 %0, %1, %2, %3;" : "=l"(r) : "l"(a), "l"(b), "l"(c));
    return r;
}

// ============================================================
// K1: partial GEMVs  key[j] = sum_i x[i] * W[i][j]
// grid = 96: m = matrix (0=w_key,1=r_key,2=erase), c = 16-row chunk
// ============================================================
__global__ void k_gemv_keys(const float* __restrict__ x,
                            const float* __restrict__ wkg,
                            const float* __restrict__ weg,
                            const float* __restrict__ rkg) {
    const int bb = blockIdx.x;
    const int m = bb >> 5, c = bb & 31;
    const float* W = (m == 0) ? wkg : ((m == 1) ? rkg : weg);
    __shared__ float sx[16];
    const int j = threadIdx.x;  // 512 threads
    if (j < 16) sx[j] = x[c * 16 + j];
    __syncthreads();
    float p = 0.f;
#pragma unroll
    for (int i = 0; i < 16; i++)
        p += sx[i] * W[(c * 16 + i) * E + j];
    g_kpart[(m * 32 + c) * E + j] = p;
}

// ============================================================
// K2: 3 blocks, one per matrix. Blocks 0/1 reduce + normalize a
// key; block 2 produces erase and zeros accumulators + out.
// ============================================================
__global__ void k_finalize_keys(float* __restrict__ out) {
    const int m = blockIdx.x;
    const int j = threadIdx.x;  // 512
    float k = 0.f;
#pragma unroll
    for (int c = 0; c < 32; c++)
        k += g_kpart[(m * 32 + c) * E + j];

    if (m == 2) {
        g_erase[j] = k;
        g_accA[j] = 0.f;
        g_accB[j] = 0.f;
        out[j] = 0.f;
        if (j < 2) g_S[j] = 0.f;
        return;
    }

    float n2 = warp_sum(k * k);
    __shared__ float rn[16];
    __shared__ float s_inv;
    const int wid = j >> 5, lane = j & 31;
    if (lane == 0) rn[wid] = n2;
    __syncthreads();
    if (j == 0) {
        float a = 0.f;
#pragma unroll
        for (int q = 0; q < 16; q++) a += rn[q];
        s_inv = rsqrtf(a);
    }
    __syncthreads();
    float* dst = (m == 0) ? g_wkeyn : g_rkeyn;
    dst[j] = k * s_inv;
}

// ============================================================
// K3: single pass over memory (256 MB).  One warp per row.
// Heavy math in packed f32x2 (FFMA2).
// ============================================================
#define PROCESS_ROW(V) do {                                                     \
    u64 dr2 = 0ull, dw2 = 0ull, nn2 = 0ull;                                     \
    _Pragma("unroll")                                                           \
    for (int i = 0; i < 8; i++) {                                               \
        dr2 = fma2(V[i], kr[i], dr2);                                           \
        dw2 = fma2(V[i], kw[i], dw2);                                           \
        nn2 = fma2(V[i], V[i], nn2);                                            \
    }                                                                           \
    float dr = hadd2(dr2), dw = hadd2(dw2), nn = hadd2(nn2);                    \
    _Pragma("unroll")                                                           \
    for (int o = 16; o; o >>= 1) {                                              \
        dr += __shfl_xor_sync(0xffffffffu, dr, o);                              \
        dw += __shfl_xor_sync(0xffffffffu, dw, o);                              \
        nn += __shfl_xor_sync(0xffffffffu, nn, o);                              \
    }                                                                           \
    const float inv = rsqrtf(nn);                                               \
    const float sr = dr * inv;                                                  \
    const float sw = dw * inv;                                                  \
    const float srw = sr * sw;                                                  \
    const u64 sr2 = pk2(sr, sr), srw2 = pk2(srw, srw);                          \
    _Pragma("unroll")                                                           \
    for (int i = 0; i < 8; i++) {                                               \
        acA[i] = fma2(V[i], sr2, acA[i]);                                       \
        acB[i] = fma2(V[i], srw2, acB[i]);                                      \
    }                                                                           \
    Sr += sr; Sw += sw;                                                         \
} while (0)

__global__ void __launch_bounds__(256, 2) k_main(const float* __restrict__ mem) {
    __shared__ u64 shA[8][256];  // 16 KB
    __shared__ u64 shB[8][256];  // 16 KB
    __shared__ float sS[16];

    const int tid = threadIdx.x;
    const int w = tid >> 5, l = tid & 31;
    const int gw = blockIdx.x * 8 + w;
    const int nW = gridDim.x * 8;

    u64 kr[8], kw[8];
    {
        const u64* rk = (const u64*)g_rkeyn;
        const u64* wk = (const u64*)g_wkeyn;
#pragma unroll
        for (int q = 0; q < 4; q++) {
            kr[2 * q]     = rk[(q * 32 + l) * 2];
            kr[2 * q + 1] = rk[(q * 32 + l) * 2 + 1];
            kw[2 * q]     = wk[(q * 32 + l) * 2];
            kw[2 * q + 1] = wk[(q * 32 + l) * 2 + 1];
        }
    }

    u64 acA[8], acB[8];
#pragma unroll
    for (int i = 0; i < 8; i++) { acA[i] = 0ull; acB[i] = 0ull; }
    float Sr = 0.f, Sw = 0.f;

    const int iters = (MEM_M - 1 - gw) / nW + 1;
    const float4* ptr = (const float4*)mem + (size_t)gw * 128 + l;
    const size_t stride = (size_t)nW * 128;

    u64 v[8], p[8];
#pragma unroll
    for (int q = 0; q < 4; q++) {
        float4 t = __ldcs(ptr + q * 32);
        v[2 * q]     = ((u64*)&t)[0];
        v[2 * q + 1] = ((u64*)&t)[1];
    }

    for (int it = 1; it < iters; ++it) {
        ptr += stride;
#pragma unroll
        for (int q = 0; q < 4; q++) {
            float4 t = __ldcs(ptr + q * 32);
            p[2 * q]     = ((u64*)&t)[0];
            p[2 * q + 1] = ((u64*)&t)[1];
        }
        PROCESS_ROW(v);
#pragma unroll
        for (int i = 0; i < 8; i++) v[i] = p[i];
    }
    PROCESS_ROW(v);

    // per-warp accumulators -> shared slices (same packed layout)
#pragma unroll
    for (int q = 0; q < 4; q++) {
        shA[w][(q * 32 + l) * 2]     = acA[2 * q];
        shA[w][(q * 32 + l) * 2 + 1] = acA[2 * q + 1];
        shB[w][(q * 32 + l) * 2]     = acB[2 * q];
        shB[w][(q * 32 + l) * 2 + 1] = acB[2 * q + 1];
    }
    if (l == 0) { sS[w] = Sr; sS[8 + w] = Sw; }
    __syncthreads();

    const float* fA = (const float*)shA;
    const float* fB = (const float*)shB;
    for (int j = tid; j < E; j += 256) {
        float a = 0.f, b = 0.f;
#pragma unroll
        for (int k = 0; k < 8; k++) {
            a += fA[k * E + j];
            b += fB[k * E + j];
        }
        atomicAdd(&g_accA[j], a);
        atomicAdd(&g_accB[j], b);
    }
    if (tid == 0) {
        float r = 0.f, ww = 0.f;
#pragma unroll
        for (int k = 0; k < 8; k++) { r += sS[k]; ww += sS[8 + k]; }
        atomicAdd(&g_S[0], r);
        atomicAdd(&g_S[1], ww);
    }
}

// ============================================================
// K4: output GEMV, atomics into d_out (zeroed by K2).
// grid 256 x 256 threads; block b: rows [4b, 4b+4).
// thread: col4 = t&127, half = t>>7 handles 2 of the 4 rows.
// ============================================================
__global__ void k_out(const float* __restrict__ x,
                      const float* __restrict__ post,
                      float* __restrict__ out) {
    __shared__ float sc[4];
    __shared__ float4 red[128];
    const int b = blockIdx.x, t = threadIdx.x;
    const int i0 = b * 4;
    if (t < 4) {
        const int i = i0 + t;
        float ci;
        if (i < E) {
            ci = x[i];
        } else {
            const int e = i - E;
            ci = (g_accA[e] - g_erase[e] * g_accB[e] / g_S[1]) / g_S[0];
        }
        sc[t] = ci;
    }
    __syncthreads();

    const int col4 = t & 127;
    const int half = t >> 7;
    const int r0 = 2 * half, r1 = 2 * half + 1;
    const float4* p4 = (const float4*)post;
    const float4 va = p4[(size_t)(i0 + r0) * 128 + col4];
    const float4 vb = p4[(size_t)(i0 + r1) * 128 + col4];
    const float c0 = sc[r0], c1 = sc[r1];
    float4 acc;
    acc.x = c0 * va.x + c1 * vb.x;
    acc.y = c0 * va.y + c1 * vb.y;
    acc.z = c0 * va.z + c1 * vb.z;
    acc.w = c0 * va.w + c1 * vb.w;

    if (half == 1) red[col4] = acc;
    __syncthreads();
    if (half == 0) {
        const float4 o = red[col4];
        atomicAdd(&out[4 * col4 + 0], acc.x + o.x);
        atomicAdd(&out[4 * col4 + 1], acc.y + o.y);
        atomicAdd(&out[4 * col4 + 2], acc.z + o.z);
        atomicAdd(&out[4 * col4 + 3], acc.w + o.w);
    }
}

// ============================================================
extern "C" void kernel_launch(void* const* d_in, const int* in_sizes, int n_in,
                              void* d_out, int out_size) {
    const float* x    = (const float*)d_in[0];
    const float* mem  = (const float*)d_in[1];
    const float* wkg  = (const float*)d_in[2];
    // d_in[3] = w_vect_gen: computed-but-unused in the reference (dead)
    const float* weg  = (const float*)d_in[4];
    const float* rkg  = (const float*)d_in[5];
    const float* post = (const float*)d_in[6];

    k_gemv_keys<<<96, 512>>>(x, wkg, weg, rkg);
    k_finalize_keys<<<3, 512>>>((float*)d_out);
    k_main<<<296, 256>>>(mem);
    k_out<<<256, 256>>>(x, post, (float*)d_out);
}